// round 6
// baseline (speedup 1.0000x reference)
#include <cuda_runtime.h>
#include <cuda_bf16.h>
#include <cstdint>

// ============================================================================
// BitLinear: y = (int8(x) @ ternary(W)^T) * (w_scale * a_scale / 127)
// Exact int8 IMMA (mma.sync m16n8k32 s8) GEMM, M=32768 N=1024 K=1024.
// Base sm_100 target: cp.async + mma.sync + ldmatrix.  No tcgen05/TMA.
// R6: xquant two-pass (low regs / high occ), 4-deep cp.async overlap,
//     streaming epilogue stores.
// ============================================================================

#define EPS_F 1e-8f

static constexpr int M_TOT = 32768;
static constexpr int N_TOT = 1024;
static constexpr int K_TOT = 1024;

static constexpr int BM = 128, BN = 128, BK = 64;
static constexpr int STAGES = 4;
static constexpr int KTILES = K_TOT / BK;            // 16
static constexpr int PITCH = 80;                     // 64B row padded to 80B
static constexpr int A_SM_BYTES = BM * PITCH;        // 10240
static constexpr int B_OFF = A_SM_BYTES;
static constexpr int STAGE_BYTES = 2 * A_SM_BYTES;   // 20480
static constexpr int SMEM_BYTES = STAGES * STAGE_BYTES; // 81920

// -------------------- device scratch (static; no allocations) ---------------
__device__ int8_t g_aq[(size_t)M_TOT * K_TOT];   // 32 MB
__device__ int8_t g_wq[(size_t)N_TOT * K_TOT];   // 1 MB
__device__ float g_ascale[M_TOT];
__device__ float g_partial[1024];
__device__ float g_wscale;

// -------------------- PTX helpers -------------------------------------------
__device__ __forceinline__ uint32_t smem_u32(const void* p) {
    uint32_t a;
    asm("{ .reg .u64 t; cvta.to.shared.u64 t, %1; cvt.u32.u64 %0, t; }"
        : "=r"(a) : "l"(p));
    return a;
}

__device__ __forceinline__ void cpasync16(uint32_t dst, const void* src) {
    asm volatile("cp.async.cg.shared.global [%0], [%1], 16;"
                 :: "r"(dst), "l"(src) : "memory");
}

__device__ __forceinline__ void cp_commit() {
    asm volatile("cp.async.commit_group;" ::: "memory");
}

__device__ __forceinline__ void cp_wait3() {
    asm volatile("cp.async.wait_group 3;" ::: "memory");
}

__device__ __forceinline__ void ldsm4(uint32_t* r, uint32_t addr) {
    asm volatile("ldmatrix.sync.aligned.m8n8.x4.shared.b16 {%0,%1,%2,%3}, [%4];"
                 : "=r"(r[0]), "=r"(r[1]), "=r"(r[2]), "=r"(r[3]) : "r"(addr));
}

__device__ __forceinline__ void mma_s8(int* c, const uint32_t* a, const uint32_t* b) {
    asm volatile(
        "mma.sync.aligned.m16n8k32.row.col.s32.s8.s8.s32 "
        "{%0,%1,%2,%3}, {%4,%5,%6,%7}, {%8,%9}, {%0,%1,%2,%3};"
        : "+r"(c[0]), "+r"(c[1]), "+r"(c[2]), "+r"(c[3])
        : "r"(a[0]), "r"(a[1]), "r"(a[2]), "r"(a[3]), "r"(b[0]), "r"(b[1]));
}

// ============================================================================
// Kernel 1: per-block |W| partial sums (deterministic tree reduce)
// ============================================================================
__global__ void __launch_bounds__(256) wabs_kernel(const float* __restrict__ w) {
    __shared__ float sm[256];
    int t = threadIdx.x;
    size_t base = (size_t)blockIdx.x * 1024;
    float s = fabsf(w[base + t]) + fabsf(w[base + t + 256])
            + fabsf(w[base + t + 512]) + fabsf(w[base + t + 768]);
    sm[t] = s;
    __syncthreads();
    for (int o = 128; o > 0; o >>= 1) {
        if (t < o) sm[t] += sm[t + o];
        __syncthreads();
    }
    if (t == 0) g_partial[blockIdx.x] = sm[0];
}

// ============================================================================
// Kernel 2: final reduce -> w_scale = mean(|W|) + eps
// ============================================================================
__global__ void __launch_bounds__(256) wreduce_kernel() {
    __shared__ float sm[256];
    int t = threadIdx.x;
    float s = g_partial[t] + g_partial[t + 256] + g_partial[t + 512] + g_partial[t + 768];
    sm[t] = s;
    __syncthreads();
    for (int o = 128; o > 0; o >>= 1) {
        if (t < o) sm[t] += sm[t + o];
        __syncthreads();
    }
    if (t == 0) g_wscale = sm[0] / 1048576.0f + EPS_F;
}

// ============================================================================
// Kernel 3: ternary weight quant -> int8  (4 elements / thread)
// ============================================================================
__global__ void __launch_bounds__(256) wquant_kernel(const float* __restrict__ w) {
    int idx = (blockIdx.x * 256 + threadIdx.x) * 4;
    float ws = g_wscale;
    float4 v = *(const float4*)(w + idx);
    int q0 = (int)fminf(fmaxf(rintf(v.x / ws), -1.0f), 1.0f);
    int q1 = (int)fminf(fmaxf(rintf(v.y / ws), -1.0f), 1.0f);
    int q2 = (int)fminf(fmaxf(rintf(v.z / ws), -1.0f), 1.0f);
    int q3 = (int)fminf(fmaxf(rintf(v.w / ws), -1.0f), 1.0f);
    uint32_t p = (uint32_t)(q0 & 0xFF) | ((uint32_t)(q1 & 0xFF) << 8)
               | ((uint32_t)(q2 & 0xFF) << 16) | ((uint32_t)(q3 & 0xFF) << 24);
    *(uint32_t*)(g_wq + idx) = p;
}

// ============================================================================
// Kernel 4: per-row activation quant -> int8.  One warp per row, 8 warps/blk.
// Two-pass: (1) stream row for max, (2) reload from L1 and quantize.
// Low register count -> full occupancy hides DRAM latency.
// ============================================================================
__global__ void __launch_bounds__(256) xquant_kernel(const float* __restrict__ x) {
    int wid = threadIdx.x >> 5, lane = threadIdx.x & 31;
    int row = blockIdx.x * 8 + wid;
    const float4* xr = (const float4*)(x + (size_t)row * 1024);

    float m = 0.0f;
#pragma unroll
    for (int i = 0; i < 8; i++) {
        float4 v = xr[i * 32 + lane];
        m = fmaxf(m, fmaxf(fmaxf(fabsf(v.x), fabsf(v.y)),
                           fmaxf(fabsf(v.z), fabsf(v.w))));
    }
#pragma unroll
    for (int o = 16; o; o >>= 1) m = fmaxf(m, __shfl_xor_sync(0xFFFFFFFFu, m, o));
    float s = m + EPS_F;
    if (lane == 0) g_ascale[row] = s;

    float inv = 127.0f / s;
    uint32_t* q = (uint32_t*)(g_aq + (size_t)row * 1024);
#pragma unroll
    for (int i = 0; i < 8; i++) {
        float4 v = xr[i * 32 + lane];       // L1 hit (row is 4KB, just read)
        int q0 = (int)rintf(fminf(fmaxf(v.x * inv, -128.0f), 127.0f));
        int q1 = (int)rintf(fminf(fmaxf(v.y * inv, -128.0f), 127.0f));
        int q2 = (int)rintf(fminf(fmaxf(v.z * inv, -128.0f), 127.0f));
        int q3 = (int)rintf(fminf(fmaxf(v.w * inv, -128.0f), 127.0f));
        uint32_t p = (uint32_t)(q0 & 0xFF) | ((uint32_t)(q1 & 0xFF) << 8)
                   | ((uint32_t)(q2 & 0xFF) << 16) | ((uint32_t)(q3 & 0xFF) << 24);
        q[i * 32 + lane] = p;
    }
}

// ============================================================================
// Kernel 5: int8 IMMA GEMM.  256 threads = 8 warps (2 m x 4 n),
// warp tile 64x32, CTA tile 128x128x64, 4-stage cp.async pipeline (4-deep).
// Fragment loads via ldmatrix.x4 (conflict-free with 80B pitch).
// ============================================================================
__global__ void __launch_bounds__(256, 2)
gemm_kernel(float* __restrict__ out) {
    extern __shared__ __align__(16) char smem[];
    int tid = threadIdx.x;
    int wid = tid >> 5, lane = tid & 31;
    int wm = wid >> 2, wn = wid & 3;           // 2 x 4 warp grid
    int g = lane >> 2, q = lane & 3;
    int m0 = (int)(blockIdx.x >> 3) * BM;
    int n0 = (int)(blockIdx.x & 7) * BN;

    // cp.async issue geometry: thread t -> row t/4, 16B chunk t%4 (x2 halves)
    int lrow = tid >> 2, lcol = tid & 3;
    const int8_t* asrc0 = g_aq + (size_t)(m0 + lrow) * K_TOT + lcol * 16;
    const int8_t* bsrc0 = g_wq + (size_t)(n0 + lrow) * K_TOT + lcol * 16;
    uint32_t sbase = smem_u32(smem);
    uint32_t adst0 = sbase + lrow * PITCH + lcol * 16;
    uint32_t bdst0 = adst0 + B_OFF;

    // ldmatrix per-lane addresses (within stage 0)
    uint32_t a_lm = sbase
        + (uint32_t)(wm * 64 + (lane & 7) + ((lane >> 3) & 1) * 8) * PITCH
        + ((lane >> 4) & 1) * 16;
    uint32_t b_lm = sbase + B_OFF
        + (uint32_t)(wn * 32 + (lane & 7) + ((lane >> 4) & 1) * 8) * PITCH
        + ((lane >> 3) & 1) * 16;

    int acc[4][4][4];
#pragma unroll
    for (int i = 0; i < 4; i++)
#pragma unroll
        for (int j = 0; j < 4; j++)
#pragma unroll
            for (int r = 0; r < 4; r++) acc[i][j][r] = 0;

    // ---- prologue: fill first STAGES-1 stages ----
#pragma unroll
    for (int s = 0; s < STAGES - 1; s++) {
        uint32_t so = (uint32_t)s * STAGE_BYTES;
        cpasync16(adst0 + so, asrc0 + s * BK);
        cpasync16(adst0 + so + 64 * PITCH, asrc0 + (size_t)64 * K_TOT + s * BK);
        cpasync16(bdst0 + so, bsrc0 + s * BK);
        cpasync16(bdst0 + so + 64 * PITCH, bsrc0 + (size_t)64 * K_TOT + s * BK);
        cp_commit();
    }

#pragma unroll 1
    for (int kt = 0; kt < KTILES; kt++) {
        __syncthreads();                    // stage (kt+3)&3 free to overwrite

        int pf = kt + STAGES - 1;
        if (pf < KTILES) {
            uint32_t so = (uint32_t)(pf & (STAGES - 1)) * STAGE_BYTES;
            cpasync16(adst0 + so, asrc0 + pf * BK);
            cpasync16(adst0 + so + 64 * PITCH, asrc0 + (size_t)64 * K_TOT + pf * BK);
            cpasync16(bdst0 + so, bsrc0 + pf * BK);
            cpasync16(bdst0 + so + 64 * PITCH, bsrc0 + (size_t)64 * K_TOT + pf * BK);
        }
        cp_commit();
        cp_wait3();                         // stage kt complete, 3 still in flight
        __syncthreads();

        uint32_t so = (uint32_t)(kt & (STAGES - 1)) * STAGE_BYTES;
        uint32_t As = a_lm + so;
        uint32_t Bs = b_lm + so;

#pragma unroll
        for (int ks = 0; ks < 2; ks++) {
            uint32_t a[4][4], b[4][2];
#pragma unroll
            for (int mb = 0; mb < 4; mb++)
                ldsm4(a[mb], As + mb * (16 * PITCH) + ks * 32);
#pragma unroll
            for (int pr = 0; pr < 2; pr++) {
                uint32_t bp[4];
                ldsm4(bp, Bs + pr * (16 * PITCH) + ks * 32);
                b[2 * pr][0] = bp[0]; b[2 * pr][1] = bp[1];
                b[2 * pr + 1][0] = bp[2]; b[2 * pr + 1][1] = bp[3];
            }
#pragma unroll
            for (int mb = 0; mb < 4; mb++)
#pragma unroll
                for (int nb = 0; nb < 4; nb++)
                    mma_s8(acc[mb][nb], a[mb], b[nb]);
        }
    }

    // ---- epilogue: dequant rescale + streaming float2 stores ----
    float wsc = g_wscale;
#pragma unroll
    for (int mb = 0; mb < 4; mb++) {
        int r0 = m0 + wm * 64 + mb * 16 + g;
        float sc0 = wsc * g_ascale[r0] / 127.0f;
        float sc1 = wsc * g_ascale[r0 + 8] / 127.0f;
        float* o0 = out + (size_t)r0 * N_TOT + n0 + wn * 32 + q * 2;
        float* o1 = o0 + (size_t)8 * N_TOT;
#pragma unroll
        for (int nb = 0; nb < 4; nb++) {
            float2 v0, v1;
            v0.x = (float)acc[mb][nb][0] * sc0;
            v0.y = (float)acc[mb][nb][1] * sc0;
            v1.x = (float)acc[mb][nb][2] * sc1;
            v1.y = (float)acc[mb][nb][3] * sc1;
            __stcs((float2*)(o0 + nb * 8), v0);
            __stcs((float2*)(o1 + nb * 8), v1);
        }
    }
}

// ============================================================================
// Host launch
// ============================================================================
extern "C" void kernel_launch(void* const* d_in, const int* in_sizes, int n_in,
                              void* d_out, int out_size) {
    (void)in_sizes; (void)n_in; (void)out_size;
    const float* x = (const float*)d_in[0];
    const float* w = (const float*)d_in[1];
    float* out = (float*)d_out;

    cudaFuncSetAttribute(gemm_kernel, cudaFuncAttributeMaxDynamicSharedMemorySize,
                         SMEM_BYTES);

    wabs_kernel<<<1024, 256>>>(w);
    wreduce_kernel<<<1, 256>>>();
    wquant_kernel<<<1024, 256>>>(w);
    xquant_kernel<<<M_TOT / 8, 256>>>(x);
    gemm_kernel<<<(M_TOT / BM) * (N_TOT / BN), 256, SMEM_BYTES>>>(out);
}

// round 7
// speedup vs baseline: 1.0748x; 1.0748x over previous
#include <cuda_runtime.h>
#include <cuda_bf16.h>
#include <cstdint>

// ============================================================================
// BitLinear: y = (int8(x) @ ternary(W)^T) * (w_scale * a_scale / 127)
// Exact int8 IMMA (mma.sync m16n8k32 s8) GEMM, M=32768 N=1024 K=1024.
// Base sm_100 target: cp.async + mma.sync + ldmatrix.  No tcgen05/TMA.
// R7: revert GEMM loop to R5 (fastest), merge wreduce into wquant,
//     __ldcs streaming reads of x in xquant (keep g_aq L2-resident for GEMM).
// ============================================================================

#define EPS_F 1e-8f

static constexpr int M_TOT = 32768;
static constexpr int N_TOT = 1024;
static constexpr int K_TOT = 1024;

static constexpr int BM = 128, BN = 128, BK = 64;
static constexpr int STAGES = 4;
static constexpr int KTILES = K_TOT / BK;            // 16
static constexpr int PITCH = 80;                     // 64B row padded to 80B
static constexpr int A_SM_BYTES = BM * PITCH;        // 10240
static constexpr int B_OFF = A_SM_BYTES;
static constexpr int STAGE_BYTES = 2 * A_SM_BYTES;   // 20480
static constexpr int SMEM_BYTES = STAGES * STAGE_BYTES; // 81920

// -------------------- device scratch (static; no allocations) ---------------
__device__ int8_t g_aq[(size_t)M_TOT * K_TOT];   // 32 MB
__device__ int8_t g_wq[(size_t)N_TOT * K_TOT];   // 1 MB
__device__ float g_ascale[M_TOT];
__device__ float g_partial[1024];
__device__ float g_wscale;

// -------------------- PTX helpers -------------------------------------------
__device__ __forceinline__ uint32_t smem_u32(const void* p) {
    uint32_t a;
    asm("{ .reg .u64 t; cvta.to.shared.u64 t, %1; cvt.u32.u64 %0, t; }"
        : "=r"(a) : "l"(p));
    return a;
}

__device__ __forceinline__ void cpasync16(uint32_t dst, const void* src) {
    asm volatile("cp.async.cg.shared.global [%0], [%1], 16;"
                 :: "r"(dst), "l"(src) : "memory");
}

__device__ __forceinline__ void cp_commit() {
    asm volatile("cp.async.commit_group;" ::: "memory");
}

__device__ __forceinline__ void cp_wait2() {
    asm volatile("cp.async.wait_group 2;" ::: "memory");
}

__device__ __forceinline__ void ldsm4(uint32_t* r, uint32_t addr) {
    asm volatile("ldmatrix.sync.aligned.m8n8.x4.shared.b16 {%0,%1,%2,%3}, [%4];"
                 : "=r"(r[0]), "=r"(r[1]), "=r"(r[2]), "=r"(r[3]) : "r"(addr));
}

__device__ __forceinline__ void mma_s8(int* c, const uint32_t* a, const uint32_t* b) {
    asm volatile(
        "mma.sync.aligned.m16n8k32.row.col.s32.s8.s8.s32 "
        "{%0,%1,%2,%3}, {%4,%5,%6,%7}, {%8,%9}, {%0,%1,%2,%3};"
        : "+r"(c[0]), "+r"(c[1]), "+r"(c[2]), "+r"(c[3])
        : "r"(a[0]), "r"(a[1]), "r"(a[2]), "r"(a[3]), "r"(b[0]), "r"(b[1]));
}

// ============================================================================
// Kernel 1: per-block |W| partial sums (deterministic tree reduce)
// ============================================================================
__global__ void __launch_bounds__(256) wabs_kernel(const float* __restrict__ w) {
    __shared__ float sm[256];
    int t = threadIdx.x;
    size_t base = (size_t)blockIdx.x * 1024;
    float s = fabsf(w[base + t]) + fabsf(w[base + t + 256])
            + fabsf(w[base + t + 512]) + fabsf(w[base + t + 768]);
    sm[t] = s;
    __syncthreads();
    for (int o = 128; o > 0; o >>= 1) {
        if (t < o) sm[t] += sm[t + o];
        __syncthreads();
    }
    if (t == 0) g_partial[blockIdx.x] = sm[0];
}

// ============================================================================
// Kernel 2: ternary weight quant -> int8.  Each block first re-derives
// w_scale from the 1024 partials (deterministic, identical in every block),
// then quantizes 1024 weights.  Block 0 publishes g_wscale for later kernels.
// ============================================================================
__global__ void __launch_bounds__(256) wquant_kernel(const float* __restrict__ w) {
    __shared__ float sm[256];
    int t = threadIdx.x;
    float s = g_partial[t] + g_partial[t + 256] + g_partial[t + 512] + g_partial[t + 768];
    sm[t] = s;
    __syncthreads();
    for (int o = 128; o > 0; o >>= 1) {
        if (t < o) sm[t] += sm[t + o];
        __syncthreads();
    }
    float ws = sm[0] / 1048576.0f + EPS_F;
    if (blockIdx.x == 0 && t == 0) g_wscale = ws;

    int idx = (blockIdx.x * 256 + t) * 4;
    float4 v = *(const float4*)(w + idx);
    int q0 = (int)fminf(fmaxf(rintf(v.x / ws), -1.0f), 1.0f);
    int q1 = (int)fminf(fmaxf(rintf(v.y / ws), -1.0f), 1.0f);
    int q2 = (int)fminf(fmaxf(rintf(v.z / ws), -1.0f), 1.0f);
    int q3 = (int)fminf(fmaxf(rintf(v.w / ws), -1.0f), 1.0f);
    uint32_t p = (uint32_t)(q0 & 0xFF) | ((uint32_t)(q1 & 0xFF) << 8)
               | ((uint32_t)(q2 & 0xFF) << 16) | ((uint32_t)(q3 & 0xFF) << 24);
    *(uint32_t*)(g_wq + idx) = p;
}

// ============================================================================
// Kernel 3: per-row activation quant -> int8.  One warp per row, 8 warps/blk.
// __ldcs: x is read-once, evict-first (keep L2 free for g_aq reuse by GEMM).
// ============================================================================
__global__ void __launch_bounds__(256) xquant_kernel(const float* __restrict__ x) {
    int wid = threadIdx.x >> 5, lane = threadIdx.x & 31;
    int row = blockIdx.x * 8 + wid;
    const float4* xr = (const float4*)(x + (size_t)row * 1024);
    float4 v[8];
    float m = 0.0f;
#pragma unroll
    for (int i = 0; i < 8; i++) {
        v[i] = __ldcs(xr + i * 32 + lane);
        m = fmaxf(m, fmaxf(fmaxf(fabsf(v[i].x), fabsf(v[i].y)),
                           fmaxf(fabsf(v[i].z), fabsf(v[i].w))));
    }
#pragma unroll
    for (int o = 16; o; o >>= 1) m = fmaxf(m, __shfl_xor_sync(0xFFFFFFFFu, m, o));
    float s = m + EPS_F;
    if (lane == 0) g_ascale[row] = s;

    float inv = 127.0f / s;
    uint32_t* q = (uint32_t*)(g_aq + (size_t)row * 1024);
#pragma unroll
    for (int i = 0; i < 8; i++) {
        int q0 = (int)rintf(fminf(fmaxf(v[i].x * inv, -128.0f), 127.0f));
        int q1 = (int)rintf(fminf(fmaxf(v[i].y * inv, -128.0f), 127.0f));
        int q2 = (int)rintf(fminf(fmaxf(v[i].z * inv, -128.0f), 127.0f));
        int q3 = (int)rintf(fminf(fmaxf(v[i].w * inv, -128.0f), 127.0f));
        uint32_t p = (uint32_t)(q0 & 0xFF) | ((uint32_t)(q1 & 0xFF) << 8)
                   | ((uint32_t)(q2 & 0xFF) << 16) | ((uint32_t)(q3 & 0xFF) << 24);
        q[i * 32 + lane] = p;
    }
}

// ============================================================================
// Kernel 4: int8 IMMA GEMM.  256 threads = 8 warps (2 m x 4 n),
// warp tile 64x32, CTA tile 128x128x64, 4-stage cp.async pipeline.
// Fragment loads via ldmatrix.x4 (conflict-free with 80B pitch).
// Mainloop structure identical to R5 (fastest measured).
// ============================================================================
__global__ void __launch_bounds__(256, 2)
gemm_kernel(float* __restrict__ out) {
    extern __shared__ __align__(16) char smem[];
    int tid = threadIdx.x;
    int wid = tid >> 5, lane = tid & 31;
    int wm = wid >> 2, wn = wid & 3;           // 2 x 4 warp grid
    int g = lane >> 2, q = lane & 3;
    int m0 = (int)(blockIdx.x >> 3) * BM;
    int n0 = (int)(blockIdx.x & 7) * BN;

    // cp.async issue geometry: thread t -> row t/4, 16B chunk t%4 (x2 halves)
    int lrow = tid >> 2, lcol = tid & 3;
    const int8_t* asrc0 = g_aq + (size_t)(m0 + lrow) * K_TOT + lcol * 16;
    const int8_t* bsrc0 = g_wq + (size_t)(n0 + lrow) * K_TOT + lcol * 16;
    uint32_t sbase = smem_u32(smem);
    uint32_t adst0 = sbase + lrow * PITCH + lcol * 16;
    uint32_t bdst0 = adst0 + B_OFF;

    // ldmatrix per-lane addresses (within stage 0)
    uint32_t a_lm = sbase
        + (uint32_t)(wm * 64 + (lane & 7) + ((lane >> 3) & 1) * 8) * PITCH
        + ((lane >> 4) & 1) * 16;
    uint32_t b_lm = sbase + B_OFF
        + (uint32_t)(wn * 32 + (lane & 7) + ((lane >> 4) & 1) * 8) * PITCH
        + ((lane >> 3) & 1) * 16;

    int acc[4][4][4];
#pragma unroll
    for (int i = 0; i < 4; i++)
#pragma unroll
        for (int j = 0; j < 4; j++)
#pragma unroll
            for (int r = 0; r < 4; r++) acc[i][j][r] = 0;

    // ---- prologue: fill first STAGES-1 stages ----
#pragma unroll
    for (int s = 0; s < STAGES - 1; s++) {
        uint32_t so = (uint32_t)s * STAGE_BYTES;
        cpasync16(adst0 + so, asrc0 + s * BK);
        cpasync16(adst0 + so + 64 * PITCH, asrc0 + (size_t)64 * K_TOT + s * BK);
        cpasync16(bdst0 + so, bsrc0 + s * BK);
        cpasync16(bdst0 + so + 64 * PITCH, bsrc0 + (size_t)64 * K_TOT + s * BK);
        cp_commit();
    }

#pragma unroll 1
    for (int kt = 0; kt < KTILES; kt++) {
        cp_wait2();
        __syncthreads();

        int pf = kt + STAGES - 1;
        if (pf < KTILES) {
            uint32_t so = (uint32_t)(pf & (STAGES - 1)) * STAGE_BYTES;
            cpasync16(adst0 + so, asrc0 + pf * BK);
            cpasync16(adst0 + so + 64 * PITCH, asrc0 + (size_t)64 * K_TOT + pf * BK);
            cpasync16(bdst0 + so, bsrc0 + pf * BK);
            cpasync16(bdst0 + so + 64 * PITCH, bsrc0 + (size_t)64 * K_TOT + pf * BK);
        }
        cp_commit();

        uint32_t so = (uint32_t)(kt & (STAGES - 1)) * STAGE_BYTES;
        uint32_t As = a_lm + so;
        uint32_t Bs = b_lm + so;

#pragma unroll
        for (int ks = 0; ks < 2; ks++) {
            uint32_t a[4][4], b[4][2];
#pragma unroll
            for (int mb = 0; mb < 4; mb++)
                ldsm4(a[mb], As + mb * (16 * PITCH) + ks * 32);
#pragma unroll
            for (int pr = 0; pr < 2; pr++) {
                uint32_t bp[4];
                ldsm4(bp, Bs + pr * (16 * PITCH) + ks * 32);
                b[2 * pr][0] = bp[0]; b[2 * pr][1] = bp[1];
                b[2 * pr + 1][0] = bp[2]; b[2 * pr + 1][1] = bp[3];
            }
#pragma unroll
            for (int mb = 0; mb < 4; mb++)
#pragma unroll
                for (int nb = 0; nb < 4; nb++)
                    mma_s8(acc[mb][nb], a[mb], b[nb]);
        }
    }

    // ---- epilogue: dequant rescale + float2 stores ----
    float wsc = g_wscale;
#pragma unroll
    for (int mb = 0; mb < 4; mb++) {
        int r0 = m0 + wm * 64 + mb * 16 + g;
        float sc0 = wsc * g_ascale[r0] / 127.0f;
        float sc1 = wsc * g_ascale[r0 + 8] / 127.0f;
        float* o0 = out + (size_t)r0 * N_TOT + n0 + wn * 32 + q * 2;
        float* o1 = o0 + (size_t)8 * N_TOT;
#pragma unroll
        for (int nb = 0; nb < 4; nb++) {
            float2 v0, v1;
            v0.x = (float)acc[mb][nb][0] * sc0;
            v0.y = (float)acc[mb][nb][1] * sc0;
            v1.x = (float)acc[mb][nb][2] * sc1;
            v1.y = (float)acc[mb][nb][3] * sc1;
            *(float2*)(o0 + nb * 8) = v0;
            *(float2*)(o1 + nb * 8) = v1;
        }
    }
}

// ============================================================================
// Host launch
// ============================================================================
extern "C" void kernel_launch(void* const* d_in, const int* in_sizes, int n_in,
                              void* d_out, int out_size) {
    (void)in_sizes; (void)n_in; (void)out_size;
    const float* x = (const float*)d_in[0];
    const float* w = (const float*)d_in[1];
    float* out = (float*)d_out;

    cudaFuncSetAttribute(gemm_kernel, cudaFuncAttributeMaxDynamicSharedMemorySize,
                         SMEM_BYTES);

    wabs_kernel<<<1024, 256>>>(w);
    wquant_kernel<<<1024, 256>>>(w);
    xquant_kernel<<<M_TOT / 8, 256>>>(x);
    gemm_kernel<<<(M_TOT / BM) * (N_TOT / BN), 256, SMEM_BYTES>>>(out);
}